// round 13
// baseline (speedup 1.0000x reference)
#include <cuda_runtime.h>
#include <cstdint>

// out[b, n, :] = (cnn[b] @ Wkv[:, 768:1536]) @ Wp + bp   (independent of n)
// image_patches and Wq are dead: softmax over kv_len=1 -> attn == 1.
//
// 2 launches:
//   chain_kernel (384 CTAs x 256 thr, ONE grid barrier):
//     phase 1: gemm1 (12 n-tiles x 32 k-splits of 64), double-buffered,
//              red.v4 -> g_v (zero on entry: static init call 1, re-zeroed
//              by bcast each call). Prologue: g_y = bias.
//     barrier
//     phase 2: CTAs 0-191: gemm2 (12 n-tiles x 16 k-splits of 48),
//              red.v4 -> bias-preloaded g_y. CTAs 192-383 exit.
//   bcast_kernel (576 CTAs x 512 thr): TMA bulk stores; zeroes g_v at end.

#define B_SZ   64
#define N_SEQ  576
#define C_DIM  768
#define K1     2048
#define LDKV   1536

#define NBLK   384
#define NT1    12              // gemm1: 12 n-tiles of 64
#define KS1    32              // gemm1: 32 k-splits of 64 -> 384 units
#define KC1    64
#define NT2    12              // gemm2: 12 n-tiles of 64
#define KS2    16              // gemm2: 16 k-splits of 48 -> 192 units
#define KC2    48

__device__ float g_v[B_SZ * C_DIM];   // zero on entry to every call
__device__ float g_y[B_SZ * C_DIM];   // set to bias by chain prologue
__device__ unsigned g_barcnt = 0;
__device__ unsigned g_bargen = 0;     // monotonic across graph replays

// ---- packed f32x2 (FFMA2) ----
__device__ __forceinline__ unsigned long long pack2(float x) {
    unsigned long long r; unsigned xi = __float_as_uint(x);
    asm("mov.b64 %0, {%1, %1};" : "=l"(r) : "r"(xi));
    return r;
}
__device__ __forceinline__ void fma2(unsigned long long& d,
                                     unsigned long long a, unsigned long long b) {
    asm("fma.rn.f32x2 %0, %1, %2, %0;" : "+l"(d) : "l"(a), "l"(b));
}
__device__ __forceinline__ float2 u2f(unsigned long long u) {
    float2 f; asm("mov.b64 {%0, %1}, %2;" : "=f"(f.x), "=f"(f.y) : "l"(u));
    return f;
}
__device__ __forceinline__ void redg_add4(float* p, float a, float b, float c, float d) {
    asm volatile("red.global.add.v4.f32 [%0], {%1, %2, %3, %4};"
                 :: "l"(p), "f"(a), "f"(b), "f"(c), "f"(d) : "memory");
}
__device__ __forceinline__ uint32_t smem_u32(const void* p) {
    uint32_t a;
    asm("{ .reg .u64 t; cvta.to.shared.u64 t, %1; cvt.u32.u64 %0, t; }" : "=r"(a) : "l"(p));
    return a;
}

// Sense-reversing grid barrier; all NBLK CTAs resident (occ 3, 12.5 KB smem).
__device__ __forceinline__ void grid_barrier() {
    __syncthreads();
    if (threadIdx.x == 0) {
        unsigned gen = *(volatile unsigned*)&g_bargen;    // read BEFORE arriving
        __threadfence();                                  // order REDGs + gen read
        unsigned old = atomicAdd(&g_barcnt, 1);
        if (old == NBLK - 1) {
            g_barcnt = 0;
            __threadfence();
            atomicAdd(&g_bargen, 1);                      // release
        } else {
            while (*(volatile unsigned*)&g_bargen == gen) { }
        }
        __threadfence();
    }
    __syncthreads();
}

// ---------------------------------------------------------------------------
// Double-buffered 64x64 tile GEMM body (round-9 proven):
//   acc += A[64 x KCHUNK] * B[KCHUNK x 64]; 4m x 4n per thread, 256 threads.
// ---------------------------------------------------------------------------
template<int KCHUNK>
__device__ __forceinline__ void gemm_body_db(
    const float* __restrict__ A, int lda,
    const float* __restrict__ Bm, int ldb,
    float (*As)[68], float (*Bs)[64],
    unsigned long long acc[4][2])
{
    const int tid = threadIdx.x;
    const int tx = tid & 15, ty = tid >> 4;
    const int m  = tid >> 2, kq = (tid & 3) * 4;   // A-load coords
    const int kb = tid >> 4, n4 = (tid & 15) * 4;  // B-load coords

    float4 aReg = *(const float4*)&A[m * lda + kq];
    float4 bReg = *(const float4*)&Bm[kb * ldb + n4];

    #pragma unroll
    for (int kt = 0; kt < KCHUNK; kt += 16) {
        As[kq + 0][m] = aReg.x; As[kq + 1][m] = aReg.y;
        As[kq + 2][m] = aReg.z; As[kq + 3][m] = aReg.w;
        *(float4*)&Bs[kb][n4] = bReg;
        __syncthreads();

        if (kt + 16 < KCHUNK) {
            aReg = *(const float4*)&A[m * lda + kt + 16 + kq];
            bReg = *(const float4*)&Bm[(kt + 16 + kb) * ldb + n4];
        }

        #pragma unroll
        for (int k = 0; k < 16; ++k) {
            float4 a = *(const float4*)&As[k][ty * 4];
            ulonglong2 b = *(const ulonglong2*)&Bs[k][tx * 4];
            unsigned long long a0 = pack2(a.x), a1 = pack2(a.y);
            unsigned long long a2 = pack2(a.z), a3 = pack2(a.w);
            fma2(acc[0][0],a0,b.x); fma2(acc[0][1],a0,b.y);
            fma2(acc[1][0],a1,b.x); fma2(acc[1][1],a1,b.y);
            fma2(acc[2][0],a2,b.x); fma2(acc[2][1],a2,b.y);
            fma2(acc[3][0],a3,b.x); fma2(acc[3][1],a3,b.y);
        }
        __syncthreads();
    }
}

// Fused chain: gemm1 -> barrier -> gemm2.
__global__ void __launch_bounds__(256, 3)
chain_kernel(const float* __restrict__ cnn, const float* __restrict__ Wkv,
             const float* __restrict__ Wp,  const float* __restrict__ bp)
{
    __shared__ float As[16][68];   // 4352 B
    __shared__ float Bs[16][64];   // 4096 B

    const int tid = threadIdx.x;
    const int cta = blockIdx.x;
    const int tx = tid & 15, ty = tid >> 4;

    // g_y = bias (consumed by phase-2 REDGs, ordered by the barrier).
    if (cta < 192 && tid < 64) {
        int idx = cta * 64 + tid;                         // 12288 float4 of g_y
        ((float4*)g_y)[idx] = ((const float4*)bp)[idx % (C_DIM / 4)];
    }

    // ---------- Phase 1: gemm1, red.v4 -> g_v ----------
    {
        int ntile = cta % NT1;
        int split = cta / NT1;
        int n0 = ntile * 64;

        unsigned long long acc[4][2];
        #pragma unroll
        for (int i = 0; i < 4; ++i) { acc[i][0] = 0ull; acc[i][1] = 0ull; }

        gemm_body_db<KC1>(cnn + split * KC1, K1,
                          Wkv + (size_t)(split * KC1) * LDKV + C_DIM + n0, LDKV,
                          As, Bs, acc);

        #pragma unroll
        for (int i = 0; i < 4; ++i) {
            float2 f0 = u2f(acc[i][0]);
            float2 f1 = u2f(acc[i][1]);
            redg_add4(g_v + (ty * 4 + i) * C_DIM + n0 + tx * 4,
                      f0.x, f0.y, f1.x, f1.y);
        }
    }
    grid_barrier();

    // ---------- Phase 2: gemm2 on CTAs 0..191, red.v4 -> g_y ----------
    if (cta < NT2 * KS2) {
        int ntile = cta % NT2;
        int split = cta / NT2;
        int n0 = ntile * 64;

        unsigned long long acc[4][2];
        #pragma unroll
        for (int i = 0; i < 4; ++i) { acc[i][0] = 0ull; acc[i][1] = 0ull; }

        gemm_body_db<KC2>(g_v + split * KC2, C_DIM,
                          Wp + (size_t)(split * KC2) * C_DIM + n0, C_DIM,
                          As, Bs, acc);

        #pragma unroll
        for (int i = 0; i < 4; ++i) {
            float2 f0 = u2f(acc[i][0]);
            float2 f1 = u2f(acc[i][1]);
            redg_add4(g_y + (ty * 4 + i) * C_DIM + n0 + tx * 4,
                      f0.x, f0.y, f1.x, f1.y);
        }
    }
}

// Broadcast g_y over N=576 via TMA bulk stores; zero g_v for the next call.
// 576 blocks x 512 threads: b = bx/9, 64 rows per block; stage 8 replicated
// rows (24 KB) once, then 8 bulk stores of 24 KB (8 rows each).
__global__ void __launch_bounds__(512)
bcast_kernel(float* __restrict__ out)
{
    __shared__ __align__(16) float ys[8 * C_DIM];   // 24 KB

    int b     = blockIdx.x / 9;
    int chunk = blockIdx.x % 9;
    const int tid = threadIdx.x;

    const float4* ysrc = (const float4*)(g_y + b * C_DIM);
    #pragma unroll
    for (int i = tid; i < 8 * (C_DIM / 4); i += 512)
        ((float4*)ys)[i] = ysrc[i % (C_DIM / 4)];
    __syncthreads();
    asm volatile("fence.proxy.async.shared::cta;" ::: "memory");

    if (tid < 8) {
        uint32_t s = smem_u32(ys);
        float* g = out + ((size_t)b * N_SEQ + chunk * 64 + tid * 8) * C_DIM;
        asm volatile("cp.async.bulk.global.shared::cta.bulk_group [%0], [%1], %2;"
                     :: "l"(g), "r"(s), "n"(8 * C_DIM * 4) : "memory");
        asm volatile("cp.async.bulk.commit_group;" ::: "memory");
        asm volatile("cp.async.bulk.wait_group 0;" ::: "memory");
    }

    // zero g_v for the next call (first 192 blocks cover 12288 float4)
    if (blockIdx.x < 192 && tid < 64) {
        ((float4*)g_v)[blockIdx.x * 64 + tid] = make_float4(0.f, 0.f, 0.f, 0.f);
    }
}

extern "C" void kernel_launch(void* const* d_in, const int* in_sizes, int n_in,
                              void* d_out, int out_size)
{
    (void)in_sizes; (void)n_in; (void)out_size;
    // Inputs: image_patches, cnn_feature_vector, Wq, Wkv, Wp, bp
    const float* cnn = (const float*)d_in[1];
    const float* Wkv = (const float*)d_in[3];
    const float* Wp  = (const float*)d_in[4];
    const float* bp  = (const float*)d_in[5];
    float* out = (float*)d_out;

    chain_kernel<<<NBLK, 256>>>(cnn, Wkv, Wp, bp);    // 384 blocks
    bcast_kernel<<<B_SZ * 9, 512>>>(out);             // 576 blocks
}